// round 1
// baseline (speedup 1.0000x reference)
#include <cuda_runtime.h>
#include <cstdint>

// ============================================================================
// SpikingNetwork: stochastic-input LIF network, T=10 steps.
//   B=512, input=3072, hidden=2048, out=512
// Strategy:
//   K0: compute the 10 per-step threefry keys (JAX split semantics)
//   K1: p=sigmoid(x) (XLA tanh-expansion), threefry uniform draws, PRE[t,b,j]
//   K2: H = PRE @ W_in^T          (one batched [5120,3072]x[3072,2048] GEMM)
//   K3: sequential LIF scan over t -> spike matrix S[t,b,h]
//   K4: O = S @ W_out^T           (one batched [5120,2048]x[2048,512] GEMM)
//   K5: s[b,o] = sum_t (O[t,b,o] + b_out[o] > 0)  -> d_out
// Exactness notes:
//   * products in both GEMMs are exact (one operand is 0/1), so only the
//     addition ORDER matters: strict left-to-right over k, single accumulator.
//   * JAX threefry "partitionable" scheme (modern default). Set
//     JAX_PARTITIONABLE 0 to switch to the legacy "original" scheme.
// ============================================================================

#define JAX_PARTITIONABLE 1

#define NB   512
#define NIN  3072
#define NHID 2048
#define NOUT 512
#define NT   10

// ---------------- device scratch (static: no allocations allowed) -----------
__device__ float    g_pre[NT * NB * NIN];    // 63 MB
__device__ float    g_H  [NT * NB * NHID];   // 42 MB
__device__ float    g_S  [NT * NB * NHID];   // 42 MB
__device__ float    g_O  [NT * NB * NOUT];   // 10.5 MB
__device__ uint32_t g_k0[NT];
__device__ uint32_t g_k1[NT];

// ---------------- threefry2x32 (JAX-exact, 20 rounds) -----------------------
__device__ __forceinline__ uint32_t rotl32(uint32_t x, int r) {
    return __funnelshift_l(x, x, r);
}

__device__ __forceinline__ void threefry2x32(uint32_t k0, uint32_t k1,
                                             uint32_t x0, uint32_t x1,
                                             uint32_t& o0, uint32_t& o1) {
    uint32_t ks2 = k0 ^ k1 ^ 0x1BD11BDAu;
    x0 += k0; x1 += k1;
#define TF_R(r) { x0 += x1; x1 = rotl32(x1, (r)); x1 ^= x0; }
    TF_R(13) TF_R(15) TF_R(26) TF_R(6)
    x0 += k1;  x1 += ks2 + 1u;
    TF_R(17) TF_R(29) TF_R(16) TF_R(24)
    x0 += ks2; x1 += k0 + 2u;
    TF_R(13) TF_R(15) TF_R(26) TF_R(6)
    x0 += k0;  x1 += k1 + 3u;
    TF_R(17) TF_R(29) TF_R(16) TF_R(24)
    x0 += k1;  x1 += ks2 + 4u;
    TF_R(13) TF_R(15) TF_R(26) TF_R(6)
    x0 += ks2; x1 += k0 + 5u;
#undef TF_R
    o0 = x0; o1 = x1;
}

// ---------------- XLA logistic: 0.5 + 0.5*tanh(0.5*x) -----------------------
// tanh via the Eigen/XLA rational approximation (f32), no fma contraction.
__device__ __forceinline__ float xla_tanh_f32(float x) {
    const float kClamp = 7.90531110763549805f;
    float ax = fabsf(x);
    float xc = fminf(fmaxf(x, -kClamp), kClamp);
    float x2 = __fmul_rn(xc, xc);
    float p;
    p = __fadd_rn(__fmul_rn(x2, -2.76076847742355e-16f), 2.00018790482477e-13f);
    p = __fadd_rn(__fmul_rn(x2, p), -8.60467152213735e-11f);
    p = __fadd_rn(__fmul_rn(x2, p),  5.12229709037114e-08f);
    p = __fadd_rn(__fmul_rn(x2, p),  1.48572235717979e-05f);
    p = __fadd_rn(__fmul_rn(x2, p),  6.37261928875436e-04f);
    p = __fadd_rn(__fmul_rn(x2, p),  4.89352455891786e-03f);
    p = __fmul_rn(xc, p);
    float q;
    q = __fadd_rn(__fmul_rn(x2, 1.19825839466702e-06f), 1.18534705686654e-04f);
    q = __fadd_rn(__fmul_rn(x2, q), 2.26843463243900e-03f);
    q = __fadd_rn(__fmul_rn(x2, q), 4.89352518554385e-03f);
    float t = __fdiv_rn(p, q);
    return (ax < 0.0004f) ? x : t;
}

__device__ __forceinline__ float xla_sigmoid_f32(float x) {
    float t = xla_tanh_f32(__fmul_rn(x, 0.5f));
    return __fadd_rn(0.5f, __fmul_rn(0.5f, t));
}

// ---------------- K0: per-step keys (JAX split semantics) -------------------
#if JAX_PARTITIONABLE
__global__ void k_keys() {
    int t = threadIdx.x;
    if (t < NT) {
        uint32_t a, b;
        threefry2x32(0u, 42u, 0u, (uint32_t)t, a, b);   // foldlike split
        g_k0[t] = a; g_k1[t] = b;
    }
}
#else
// original split: counts = iota(2*T); x0 = counts[0:T], x1 = counts[T:2T]
// flat result r[q]=out0(pair q), r[T+q]=out1(pair q); key_t = (r[2t], r[2t+1])
__device__ __forceinline__ uint32_t split_orig_elem(int q) {
    uint32_t a, b;
    if (q < NT) { threefry2x32(0u, 42u, (uint32_t)q, (uint32_t)(NT + q), a, b); return a; }
    else        { threefry2x32(0u, 42u, (uint32_t)(q - NT), (uint32_t)q, a, b); return b; }
}
__global__ void k_keys() {
    int t = threadIdx.x;
    if (t < NT) {
        g_k0[t] = split_orig_elem(2 * t);
        g_k1[t] = split_orig_elem(2 * t + 1);
    }
}
#endif

// ---------------- K1: p + stochastic input spikes ---------------------------
__global__ __launch_bounds__(256) void k_gen(const float* __restrict__ x) {
    int idx = blockIdx.x * blockDim.x + threadIdx.x;   // flat over (b, j)
    if (idx >= NB * NIN) return;
    float p = xla_sigmoid_f32(x[idx]);
#pragma unroll
    for (int t = 0; t < NT; t++) {
        uint32_t k0 = g_k0[t], k1 = g_k1[t];
        uint32_t bits;
#if JAX_PARTITIONABLE
        uint32_t a, b;
        threefry2x32(k0, k1, 0u, (uint32_t)idx, a, b);
        bits = a ^ b;
#else
        const uint32_t half = (NB * NIN) / 2;
        uint32_t a, b;
        if ((uint32_t)idx < half) { threefry2x32(k0, k1, (uint32_t)idx, half + (uint32_t)idx, a, b); bits = a; }
        else                      { threefry2x32(k0, k1, (uint32_t)idx - half, (uint32_t)idx, a, b); bits = b; }
#endif
        float u = __uint_as_float((bits >> 9) | 0x3F800000u) - 1.0f;
        g_pre[(size_t)t * (NB * NIN) + idx] = (u < p) ? 1.0f : 0.0f;
    }
}

// ---------------- tiled NT-GEMM: C[m,n] = sum_k A[m,k]*B[n,k] ---------------
// 128x128 tile, BK=16, 256 threads, 8x8 micro-tile. Strict ascending-k,
// single accumulator per output element (left-to-right fp32 sum).
__global__ __launch_bounds__(256)
void gemm_nt(const float* __restrict__ A, const float* __restrict__ Bm,
             float* __restrict__ C, int M, int N, int K) {
    __shared__ float As[16][128];
    __shared__ float Bs[16][128];
    const int tid = threadIdx.x;
    const int tx  = tid & 15;   // -> n micro-tile
    const int ty  = tid >> 4;   // -> m micro-tile
    const int m0  = blockIdx.y * 128;
    const int n0  = blockIdx.x * 128;

    float acc[8][8];
#pragma unroll
    for (int i = 0; i < 8; i++)
#pragma unroll
        for (int j = 0; j < 8; j++) acc[i][j] = 0.0f;

    for (int kb = 0; kb < K; kb += 16) {
#pragma unroll
        for (int it = 0; it < 2; it++) {
            int q  = tid * 2 + it;
            int r  = q >> 2;
            int kc = (q & 3) * 4;
            float4 av = *reinterpret_cast<const float4*>(A + (size_t)(m0 + r) * K + kb + kc);
            As[kc + 0][r] = av.x; As[kc + 1][r] = av.y;
            As[kc + 2][r] = av.z; As[kc + 3][r] = av.w;
            float4 bv = *reinterpret_cast<const float4*>(Bm + (size_t)(n0 + r) * K + kb + kc);
            Bs[kc + 0][r] = bv.x; Bs[kc + 1][r] = bv.y;
            Bs[kc + 2][r] = bv.z; Bs[kc + 3][r] = bv.w;
        }
        __syncthreads();
#pragma unroll
        for (int k = 0; k < 16; k++) {
            float4 a0 = *reinterpret_cast<const float4*>(&As[k][ty * 8]);
            float4 a1 = *reinterpret_cast<const float4*>(&As[k][ty * 8 + 4]);
            float4 b0 = *reinterpret_cast<const float4*>(&Bs[k][tx * 8]);
            float4 b1 = *reinterpret_cast<const float4*>(&Bs[k][tx * 8 + 4]);
            float a[8] = {a0.x, a0.y, a0.z, a0.w, a1.x, a1.y, a1.z, a1.w};
            float b[8] = {b0.x, b0.y, b0.z, b0.w, b1.x, b1.y, b1.z, b1.w};
#pragma unroll
            for (int i = 0; i < 8; i++)
#pragma unroll
                for (int j = 0; j < 8; j++)
                    acc[i][j] = __fmaf_rn(a[i], b[j], acc[i][j]);
        }
        __syncthreads();
    }

#pragma unroll
    for (int i = 0; i < 8; i++) {
        float4 c0 = make_float4(acc[i][0], acc[i][1], acc[i][2], acc[i][3]);
        float4 c1 = make_float4(acc[i][4], acc[i][5], acc[i][6], acc[i][7]);
        float* crow = C + (size_t)(m0 + ty * 8 + i) * N + n0 + tx * 8;
        *reinterpret_cast<float4*>(crow)     = c0;
        *reinterpret_cast<float4*>(crow + 4) = c1;
    }
}

// ---------------- K3: sequential LIF scan -----------------------------------
__global__ __launch_bounds__(256) void k_lif() {
    int i = blockIdx.x * blockDim.x + threadIdx.x;     // flat over (b, hid)
    if (i >= NB * NHID) return;
    float v = 0.0f;
#pragma unroll
    for (int t = 0; t < NT; t++) {
        float h = g_H[(size_t)t * (NB * NHID) + i];
        v = __fadd_rn(__fmul_rn(v, 0.3f), h);          // no fma contraction
        float sp = (v >= 1.0f) ? 1.0f : 0.0f;
        if (v >= 1.0f) v = 0.0f;
        g_S[(size_t)t * (NB * NHID) + i] = sp;
    }
}

// ---------------- K5: output spike counting ---------------------------------
__global__ __launch_bounds__(256) void k_count(const float* __restrict__ b_out,
                                               float* __restrict__ out) {
    int i = blockIdx.x * blockDim.x + threadIdx.x;     // flat over (b, o)
    if (i >= NB * NOUT) return;
    int o = i & (NOUT - 1);
    float bo = b_out[o];
    float s = 0.0f;
#pragma unroll
    for (int t = 0; t < NT; t++) {
        float val = __fadd_rn(g_O[(size_t)t * (NB * NOUT) + i], bo);
        s += (val > 0.0f) ? 1.0f : 0.0f;
    }
    out[i] = s;
}

// ---------------- launch ----------------------------------------------------
extern "C" void kernel_launch(void* const* d_in, const int* in_sizes, int n_in,
                              void* d_out, int out_size) {
    const float* x     = (const float*)d_in[0];
    const float* W_in  = (const float*)d_in[1];
    const float* W_out = (const float*)d_in[2];
    const float* b_out = (const float*)d_in[3];
    float* out = (float*)d_out;

    void *p_pre, *p_H, *p_S, *p_O;
    cudaGetSymbolAddress(&p_pre, g_pre);
    cudaGetSymbolAddress(&p_H,   g_H);
    cudaGetSymbolAddress(&p_S,   g_S);
    cudaGetSymbolAddress(&p_O,   g_O);

    k_keys<<<1, 32>>>();
    k_gen<<<(NB * NIN + 255) / 256, 256>>>(x);

    // H[5120, 2048] = PRE[5120, 3072] @ W_in[2048, 3072]^T
    {
        dim3 grid(NHID / 128, (NT * NB) / 128);
        gemm_nt<<<grid, 256>>>((const float*)p_pre, W_in, (float*)p_H,
                               NT * NB, NHID, NIN);
    }

    k_lif<<<(NB * NHID + 255) / 256, 256>>>();

    // O[5120, 512] = S[5120, 2048] @ W_out[512, 2048]^T
    {
        dim3 grid(NOUT / 128, (NT * NB) / 128);
        gemm_nt<<<grid, 256>>>((const float*)p_S, W_out, (float*)p_O,
                               NT * NB, NOUT, NHID);
    }

    k_count<<<(NB * NOUT + 255) / 256, 256>>>(b_out, out);
}

// round 2
// speedup vs baseline: 1.0473x; 1.0473x over previous
#include <cuda_runtime.h>
#include <cstdint>

// ============================================================================
// SpikingNetwork: stochastic-input LIF network, T=10 steps.
//   B=512, input=3072, hidden=2048, out=512
// Pipeline:
//   K0: per-step threefry keys (JAX partitionable split)
//   K1: p=sigmoid(x) (XLA tanh expansion) + threefry draws -> PRE[t,b,j]
//   K2: H = PRE @ W_in^T   ([5120,3072]x[3072,2048] fp32 SGEMM)
//   K3: sequential LIF scan -> S[t,b,h]
//   K4: O = S @ W_out^T    ([5120,2048]x[2048,512] fp32 SGEMM)
//   K5: count out>0 over t -> d_out
// EXACTNESS CONTRACT (verified rel_err==0.0 in R1):
//   strict ascending-k, single fp32 accumulator per output element.
//   Products are exact (0/1 operand) so FFMA == reference's mul+add.
//   DO NOT reassociate (no split-k, no tensor cores).
// ============================================================================

#define JAX_PARTITIONABLE 1

#define NB   512
#define NIN  3072
#define NHID 2048
#define NOUT 512
#define NT   10

__device__ float    g_pre[NT * NB * NIN];
__device__ float    g_H  [NT * NB * NHID];
__device__ float    g_S  [NT * NB * NHID];
__device__ float    g_O  [NT * NB * NOUT];
__device__ uint32_t g_k0[NT];
__device__ uint32_t g_k1[NT];

// ---------------- threefry2x32 (JAX-exact, 20 rounds) -----------------------
__device__ __forceinline__ uint32_t rotl32(uint32_t x, int r) {
    return __funnelshift_l(x, x, r);
}

__device__ __forceinline__ void threefry2x32(uint32_t k0, uint32_t k1,
                                             uint32_t x0, uint32_t x1,
                                             uint32_t& o0, uint32_t& o1) {
    uint32_t ks2 = k0 ^ k1 ^ 0x1BD11BDAu;
    x0 += k0; x1 += k1;
#define TF_R(r) { x0 += x1; x1 = rotl32(x1, (r)); x1 ^= x0; }
    TF_R(13) TF_R(15) TF_R(26) TF_R(6)
    x0 += k1;  x1 += ks2 + 1u;
    TF_R(17) TF_R(29) TF_R(16) TF_R(24)
    x0 += ks2; x1 += k0 + 2u;
    TF_R(13) TF_R(15) TF_R(26) TF_R(6)
    x0 += k0;  x1 += k1 + 3u;
    TF_R(17) TF_R(29) TF_R(16) TF_R(24)
    x0 += k1;  x1 += ks2 + 4u;
    TF_R(13) TF_R(15) TF_R(26) TF_R(6)
    x0 += ks2; x1 += k0 + 5u;
#undef TF_R
    o0 = x0; o1 = x1;
}

// ---------------- XLA logistic: 0.5 + 0.5*tanh(0.5*x) -----------------------
__device__ __forceinline__ float xla_tanh_f32(float x) {
    const float kClamp = 7.90531110763549805f;
    float ax = fabsf(x);
    float xc = fminf(fmaxf(x, -kClamp), kClamp);
    float x2 = __fmul_rn(xc, xc);
    float p;
    p = __fadd_rn(__fmul_rn(x2, -2.76076847742355e-16f), 2.00018790482477e-13f);
    p = __fadd_rn(__fmul_rn(x2, p), -8.60467152213735e-11f);
    p = __fadd_rn(__fmul_rn(x2, p),  5.12229709037114e-08f);
    p = __fadd_rn(__fmul_rn(x2, p),  1.48572235717979e-05f);
    p = __fadd_rn(__fmul_rn(x2, p),  6.37261928875436e-04f);
    p = __fadd_rn(__fmul_rn(x2, p),  4.89352455891786e-03f);
    p = __fmul_rn(xc, p);
    float q;
    q = __fadd_rn(__fmul_rn(x2, 1.19825839466702e-06f), 1.18534705686654e-04f);
    q = __fadd_rn(__fmul_rn(x2, q), 2.26843463243900e-03f);
    q = __fadd_rn(__fmul_rn(x2, q), 4.89352518554385e-03f);
    float t = __fdiv_rn(p, q);
    return (ax < 0.0004f) ? x : t;
}

__device__ __forceinline__ float xla_sigmoid_f32(float x) {
    float t = xla_tanh_f32(__fmul_rn(x, 0.5f));
    return __fadd_rn(0.5f, __fmul_rn(0.5f, t));
}

// ---------------- K0: per-step keys -----------------------------------------
#if JAX_PARTITIONABLE
__global__ void k_keys() {
    int t = threadIdx.x;
    if (t < NT) {
        uint32_t a, b;
        threefry2x32(0u, 42u, 0u, (uint32_t)t, a, b);
        g_k0[t] = a; g_k1[t] = b;
    }
}
#else
__device__ __forceinline__ uint32_t split_orig_elem(int q) {
    uint32_t a, b;
    if (q < NT) { threefry2x32(0u, 42u, (uint32_t)q, (uint32_t)(NT + q), a, b); return a; }
    else        { threefry2x32(0u, 42u, (uint32_t)(q - NT), (uint32_t)q, a, b); return b; }
}
__global__ void k_keys() {
    int t = threadIdx.x;
    if (t < NT) {
        g_k0[t] = split_orig_elem(2 * t);
        g_k1[t] = split_orig_elem(2 * t + 1);
    }
}
#endif

// ---------------- K1: p + stochastic input spikes ---------------------------
__global__ __launch_bounds__(256) void k_gen(const float* __restrict__ x) {
    int idx = blockIdx.x * blockDim.x + threadIdx.x;
    if (idx >= NB * NIN) return;
    float p = xla_sigmoid_f32(x[idx]);
#pragma unroll
    for (int t = 0; t < NT; t++) {
        uint32_t k0 = g_k0[t], k1 = g_k1[t];
        uint32_t bits;
#if JAX_PARTITIONABLE
        uint32_t a, b;
        threefry2x32(k0, k1, 0u, (uint32_t)idx, a, b);
        bits = a ^ b;
#else
        const uint32_t half = (NB * NIN) / 2;
        uint32_t a, b;
        if ((uint32_t)idx < half) { threefry2x32(k0, k1, (uint32_t)idx, half + (uint32_t)idx, a, b); bits = a; }
        else                      { threefry2x32(k0, k1, (uint32_t)idx - half, (uint32_t)idx, a, b); bits = b; }
#endif
        float u = __uint_as_float((bits >> 9) | 0x3F800000u) - 1.0f;
        g_pre[(size_t)t * (NB * NIN) + idx] = (u < p) ? 1.0f : 0.0f;
    }
}

// ---------------- pipelined SGEMM: C[m,n] = sum_k A[m,k]*B[n,k] -------------
// 128x128x16 tile, 256 threads, 8x8 microtile. Double-buffered smem (1 sync
// per slab), global prefetch into regs during compute, register fragment
// double-buffering. Strict ascending-k, single accumulator per output.
__global__ __launch_bounds__(256)
void gemm_nt(const float* __restrict__ A, const float* __restrict__ Bm,
             float* __restrict__ C, int M, int N, int K) {
    __shared__ float As[2][16][128];
    __shared__ float Bs[2][16][128];

    const int tid = threadIdx.x;
    const int m0  = blockIdx.y * 128;
    const int n0  = blockIdx.x * 128;

    // Global-load mapping: thread -> (row = tid>>1, kc = (tid&1)*8), 8 floats.
    const int lrow = tid >> 1;
    const int lkc  = (tid & 1) * 8;
    const float* Ag = A + (size_t)(m0 + lrow) * K + lkc;
    const float* Bg = Bm + (size_t)(n0 + lrow) * K + lkc;

    // Compute mapping: warps 2(m) x 4(n); lanes 8(m) x 4(n); 8x8 per thread.
    const int warp = tid >> 5;
    const int lane = tid & 31;
    const int tm = (warp & 1) * 64 + (lane & 7) * 8;   // m offset in tile
    const int tn = (warp >> 1) * 32 + (lane >> 3) * 8; // n offset in tile

    float acc[8][8];
#pragma unroll
    for (int i = 0; i < 8; i++)
#pragma unroll
        for (int j = 0; j < 8; j++) acc[i][j] = 0.0f;

    // -- preload first slab into registers, store to stage 0
    float4 pa0 = *reinterpret_cast<const float4*>(Ag);
    float4 pa1 = *reinterpret_cast<const float4*>(Ag + 4);
    float4 pb0 = *reinterpret_cast<const float4*>(Bg);
    float4 pb1 = *reinterpret_cast<const float4*>(Bg + 4);

    int stage = 0;
    {
        As[0][lkc + 0][lrow] = pa0.x; As[0][lkc + 1][lrow] = pa0.y;
        As[0][lkc + 2][lrow] = pa0.z; As[0][lkc + 3][lrow] = pa0.w;
        As[0][lkc + 4][lrow] = pa1.x; As[0][lkc + 5][lrow] = pa1.y;
        As[0][lkc + 6][lrow] = pa1.z; As[0][lkc + 7][lrow] = pa1.w;
        Bs[0][lkc + 0][lrow] = pb0.x; Bs[0][lkc + 1][lrow] = pb0.y;
        Bs[0][lkc + 2][lrow] = pb0.z; Bs[0][lkc + 3][lrow] = pb0.w;
        Bs[0][lkc + 4][lrow] = pb1.x; Bs[0][lkc + 5][lrow] = pb1.y;
        Bs[0][lkc + 6][lrow] = pb1.z; Bs[0][lkc + 7][lrow] = pb1.w;
    }
    __syncthreads();

    for (int kb = 0; kb < K; kb += 16) {
        const bool has_next = (kb + 16) < K;
        // prefetch next slab (global -> regs) before compute
        if (has_next) {
            pa0 = *reinterpret_cast<const float4*>(Ag + kb + 16);
            pa1 = *reinterpret_cast<const float4*>(Ag + kb + 20);
            pb0 = *reinterpret_cast<const float4*>(Bg + kb + 16);
            pb1 = *reinterpret_cast<const float4*>(Bg + kb + 20);
        }

        // compute slab with register fragment double-buffering
        float af[2][8], bf[2][8];
        {
            float4 a0 = *reinterpret_cast<const float4*>(&As[stage][0][tm]);
            float4 a1 = *reinterpret_cast<const float4*>(&As[stage][0][tm + 4]);
            float4 b0 = *reinterpret_cast<const float4*>(&Bs[stage][0][tn]);
            float4 b1 = *reinterpret_cast<const float4*>(&Bs[stage][0][tn + 4]);
            af[0][0]=a0.x; af[0][1]=a0.y; af[0][2]=a0.z; af[0][3]=a0.w;
            af[0][4]=a1.x; af[0][5]=a1.y; af[0][6]=a1.z; af[0][7]=a1.w;
            bf[0][0]=b0.x; bf[0][1]=b0.y; bf[0][2]=b0.z; bf[0][3]=b0.w;
            bf[0][4]=b1.x; bf[0][5]=b1.y; bf[0][6]=b1.z; bf[0][7]=b1.w;
        }
#pragma unroll
        for (int k = 0; k < 16; k++) {
            const int cur = k & 1, nxt = cur ^ 1;
            if (k < 15) {
                float4 a0 = *reinterpret_cast<const float4*>(&As[stage][k + 1][tm]);
                float4 a1 = *reinterpret_cast<const float4*>(&As[stage][k + 1][tm + 4]);
                float4 b0 = *reinterpret_cast<const float4*>(&Bs[stage][k + 1][tn]);
                float4 b1 = *reinterpret_cast<const float4*>(&Bs[stage][k + 1][tn + 4]);
                af[nxt][0]=a0.x; af[nxt][1]=a0.y; af[nxt][2]=a0.z; af[nxt][3]=a0.w;
                af[nxt][4]=a1.x; af[nxt][5]=a1.y; af[nxt][6]=a1.z; af[nxt][7]=a1.w;
                bf[nxt][0]=b0.x; bf[nxt][1]=b0.y; bf[nxt][2]=b0.z; bf[nxt][3]=b0.w;
                bf[nxt][4]=b1.x; bf[nxt][5]=b1.y; bf[nxt][6]=b1.z; bf[nxt][7]=b1.w;
            }
#pragma unroll
            for (int i = 0; i < 8; i++)
#pragma unroll
                for (int j = 0; j < 8; j++)
                    acc[i][j] = __fmaf_rn(af[cur][i], bf[cur][j], acc[i][j]);
        }

        // stage the prefetched slab and flip
        if (has_next) {
            const int ns = stage ^ 1;
            As[ns][lkc + 0][lrow] = pa0.x; As[ns][lkc + 1][lrow] = pa0.y;
            As[ns][lkc + 2][lrow] = pa0.z; As[ns][lkc + 3][lrow] = pa0.w;
            As[ns][lkc + 4][lrow] = pa1.x; As[ns][lkc + 5][lrow] = pa1.y;
            As[ns][lkc + 6][lrow] = pa1.z; As[ns][lkc + 7][lrow] = pa1.w;
            Bs[ns][lkc + 0][lrow] = pb0.x; Bs[ns][lkc + 1][lrow] = pb0.y;
            Bs[ns][lkc + 2][lrow] = pb0.z; Bs[ns][lkc + 3][lrow] = pb0.w;
            Bs[ns][lkc + 4][lrow] = pb1.x; Bs[ns][lkc + 5][lrow] = pb1.y;
            Bs[ns][lkc + 6][lrow] = pb1.z; Bs[ns][lkc + 7][lrow] = pb1.w;
            __syncthreads();
            stage = ns;
        }
    }

#pragma unroll
    for (int i = 0; i < 8; i++) {
        float4 c0 = make_float4(acc[i][0], acc[i][1], acc[i][2], acc[i][3]);
        float4 c1 = make_float4(acc[i][4], acc[i][5], acc[i][6], acc[i][7]);
        float* crow = C + (size_t)(m0 + tm + i) * N + n0 + tn;
        *reinterpret_cast<float4*>(crow)     = c0;
        *reinterpret_cast<float4*>(crow + 4) = c1;
    }
}

// ---------------- K3: sequential LIF scan -----------------------------------
__global__ __launch_bounds__(256) void k_lif() {
    int i = blockIdx.x * blockDim.x + threadIdx.x;
    if (i >= NB * NHID) return;
    float v = 0.0f;
#pragma unroll
    for (int t = 0; t < NT; t++) {
        float h = g_H[(size_t)t * (NB * NHID) + i];
        v = __fadd_rn(__fmul_rn(v, 0.3f), h);
        float sp = (v >= 1.0f) ? 1.0f : 0.0f;
        if (v >= 1.0f) v = 0.0f;
        g_S[(size_t)t * (NB * NHID) + i] = sp;
    }
}

// ---------------- K5: output spike counting ---------------------------------
__global__ __launch_bounds__(256) void k_count(const float* __restrict__ b_out,
                                               float* __restrict__ out) {
    int i = blockIdx.x * blockDim.x + threadIdx.x;
    if (i >= NB * NOUT) return;
    int o = i & (NOUT - 1);
    float bo = b_out[o];
    float s = 0.0f;
#pragma unroll
    for (int t = 0; t < NT; t++) {
        float val = __fadd_rn(g_O[(size_t)t * (NB * NOUT) + i], bo);
        s += (val > 0.0f) ? 1.0f : 0.0f;
    }
    out[i] = s;
}

// ---------------- launch ----------------------------------------------------
extern "C" void kernel_launch(void* const* d_in, const int* in_sizes, int n_in,
                              void* d_out, int out_size) {
    const float* x     = (const float*)d_in[0];
    const float* W_in  = (const float*)d_in[1];
    const float* W_out = (const float*)d_in[2];
    const float* b_out = (const float*)d_in[3];
    float* out = (float*)d_out;

    void *p_pre, *p_H, *p_S, *p_O;
    cudaGetSymbolAddress(&p_pre, g_pre);
    cudaGetSymbolAddress(&p_H,   g_H);
    cudaGetSymbolAddress(&p_S,   g_S);
    cudaGetSymbolAddress(&p_O,   g_O);

    k_keys<<<1, 32>>>();
    k_gen<<<(NB * NIN + 255) / 256, 256>>>(x);

    {   // H[5120,2048] = PRE[5120,3072] @ W_in[2048,3072]^T
        dim3 grid(NHID / 128, (NT * NB) / 128);
        gemm_nt<<<grid, 256>>>((const float*)p_pre, W_in, (float*)p_H,
                               NT * NB, NHID, NIN);
    }

    k_lif<<<(NB * NHID + 255) / 256, 256>>>();

    {   // O[5120,512] = S[5120,2048] @ W_out[512,2048]^T
        dim3 grid(NOUT / 128, (NT * NB) / 128);
        gemm_nt<<<grid, 256>>>((const float*)p_S, W_out, (float*)p_O,
                               NT * NB, NOUT, NHID);
    }

    k_count<<<(NB * NOUT + 255) / 256, 256>>>(b_out, out);
}

// round 3
// speedup vs baseline: 1.3101x; 1.2509x over previous
#include <cuda_runtime.h>
#include <cstdint>

// ============================================================================
// SpikingNetwork, T=10. B=512, input=3072, hidden=2048, out=512
// All GEMM operands pre-transposed so A,B are contiguous along M/N:
//   g_preT [3072][5120] : PRE^T      (k_gen writes transposed via smem tile)
//   g_WinT [3072][2048] : W_in^T     (one-time transpose kernel)
//   g_H    [5120][2048] : H = PRE @ W_in^T (row-major)
//   g_ST   [2048][5120] : S^T        (k_lif writes transposed)
//   g_WoutT[2048][ 512] : W_out^T
//   g_O    [5120][ 512] : O
// GEMM (TT form): C[m,n] = sum_k A[k][m] * B[k][n], ascending k, one fp32
// accumulator per output -> bit-exact vs reference (verified rel_err==0.0).
// ============================================================================

#define NB   512
#define NIN  3072
#define NHID 2048
#define NOUT 512
#define NT   10
#define NM   (NT * NB)     // 5120

__device__ float    g_preT [NIN  * NM];
__device__ float    g_WinT [NIN  * NHID];
__device__ float    g_H    [NM   * NHID];
__device__ float    g_ST   [NHID * NM];
__device__ float    g_WoutT[NHID * NOUT];
__device__ float    g_O    [NM   * NOUT];
__device__ uint32_t g_k0[NT];
__device__ uint32_t g_k1[NT];

// ---------------- threefry2x32 (JAX-exact, 20 rounds) -----------------------
__device__ __forceinline__ uint32_t rotl32(uint32_t x, int r) {
    return __funnelshift_l(x, x, r);
}
__device__ __forceinline__ void threefry2x32(uint32_t k0, uint32_t k1,
                                             uint32_t x0, uint32_t x1,
                                             uint32_t& o0, uint32_t& o1) {
    uint32_t ks2 = k0 ^ k1 ^ 0x1BD11BDAu;
    x0 += k0; x1 += k1;
#define TF_R(r) { x0 += x1; x1 = rotl32(x1, (r)); x1 ^= x0; }
    TF_R(13) TF_R(15) TF_R(26) TF_R(6)
    x0 += k1;  x1 += ks2 + 1u;
    TF_R(17) TF_R(29) TF_R(16) TF_R(24)
    x0 += ks2; x1 += k0 + 2u;
    TF_R(13) TF_R(15) TF_R(26) TF_R(6)
    x0 += k0;  x1 += k1 + 3u;
    TF_R(17) TF_R(29) TF_R(16) TF_R(24)
    x0 += k1;  x1 += ks2 + 4u;
    TF_R(13) TF_R(15) TF_R(26) TF_R(6)
    x0 += ks2; x1 += k0 + 5u;
#undef TF_R
    o0 = x0; o1 = x1;
}

// ---------------- XLA logistic: 0.5 + 0.5*tanh(0.5*x) -----------------------
__device__ __forceinline__ float xla_tanh_f32(float x) {
    const float kClamp = 7.90531110763549805f;
    float ax = fabsf(x);
    float xc = fminf(fmaxf(x, -kClamp), kClamp);
    float x2 = __fmul_rn(xc, xc);
    float p;
    p = __fadd_rn(__fmul_rn(x2, -2.76076847742355e-16f), 2.00018790482477e-13f);
    p = __fadd_rn(__fmul_rn(x2, p), -8.60467152213735e-11f);
    p = __fadd_rn(__fmul_rn(x2, p),  5.12229709037114e-08f);
    p = __fadd_rn(__fmul_rn(x2, p),  1.48572235717979e-05f);
    p = __fadd_rn(__fmul_rn(x2, p),  6.37261928875436e-04f);
    p = __fadd_rn(__fmul_rn(x2, p),  4.89352455891786e-03f);
    p = __fmul_rn(xc, p);
    float q;
    q = __fadd_rn(__fmul_rn(x2, 1.19825839466702e-06f), 1.18534705686654e-04f);
    q = __fadd_rn(__fmul_rn(x2, q), 2.26843463243900e-03f);
    q = __fadd_rn(__fmul_rn(x2, q), 4.89352518554385e-03f);
    float t = __fdiv_rn(p, q);
    return (ax < 0.0004f) ? x : t;
}
__device__ __forceinline__ float xla_sigmoid_f32(float x) {
    float t = xla_tanh_f32(__fmul_rn(x, 0.5f));
    return __fadd_rn(0.5f, __fmul_rn(0.5f, t));
}

// ---------------- cp.async helpers ------------------------------------------
__device__ __forceinline__ void cp16(void* dst_smem, const void* src) {
    uint32_t d = (uint32_t)__cvta_generic_to_shared(dst_smem);
    asm volatile("cp.async.cg.shared.global [%0], [%1], 16;\n" :: "r"(d), "l"(src));
}
__device__ __forceinline__ void cp_commit() {
    asm volatile("cp.async.commit_group;\n");
}
__device__ __forceinline__ void cp_wait0() {
    asm volatile("cp.async.wait_group 0;\n");
}

// ---------------- K0: per-step keys (partitionable split) -------------------
__global__ void k_keys() {
    int t = threadIdx.x;
    if (t < NT) {
        uint32_t a, b;
        threefry2x32(0u, 42u, 0u, (uint32_t)t, a, b);
        g_k0[t] = a; g_k1[t] = b;
    }
}

// ---------------- one-time weight transposes --------------------------------
// dst[C][R] = src[R][C] ; grid (C/32, R/32), 256 threads (32x8)
__global__ __launch_bounds__(256) void k_transpose(const float* __restrict__ src,
                                                   float* __restrict__ dst,
                                                   int R, int C) {
    __shared__ float tile[32][33];
    int c0 = blockIdx.x * 32, r0 = blockIdx.y * 32;
    int x = threadIdx.x & 31, y = threadIdx.x >> 5;
#pragma unroll
    for (int i = 0; i < 4; i++)
        tile[y + 8 * i][x] = src[(size_t)(r0 + y + 8 * i) * C + c0 + x];
    __syncthreads();
#pragma unroll
    for (int i = 0; i < 4; i++)
        dst[(size_t)(c0 + y + 8 * i) * R + r0 + x] = tile[x][y + 8 * i];
}

// ---------------- K1: spikes -> g_preT (transposed) -------------------------
// grid (NIN/32, NB/32), 256 threads. Phase1: thread=(b_l,j_l) computes 10-bit
// spike mask (threefry idx = b*NIN+j, JAX order). Phase2: transposed write,
// lanes sweep b -> coalesced stores into g_preT[j][t*NB+b].
__global__ __launch_bounds__(256) void k_gen(const float* __restrict__ x) {
    __shared__ uint32_t msk[32][33];
    const int j0 = blockIdx.x * 32, b0 = blockIdx.y * 32;
    const int tid = threadIdx.x;

    uint32_t kk0[NT], kk1[NT];
#pragma unroll
    for (int t = 0; t < NT; t++) { kk0[t] = g_k0[t]; kk1[t] = g_k1[t]; }

    const int jl = tid & 31;
#pragma unroll
    for (int r = 0; r < 4; r++) {
        const int bl = (tid >> 5) * 4 + r;
        const int b = b0 + bl, j = j0 + jl;
        const uint32_t idx = (uint32_t)(b * NIN + j);
        float p = xla_sigmoid_f32(x[(size_t)b * NIN + j]);
        uint32_t m = 0;
#pragma unroll
        for (int t = 0; t < NT; t++) {
            uint32_t a, bb;
            threefry2x32(kk0[t], kk1[t], 0u, idx, a, bb);
            uint32_t bits = a ^ bb;
            float u = __uint_as_float((bits >> 9) | 0x3F800000u) - 1.0f;
            m |= (u < p) ? (1u << t) : 0u;
        }
        msk[bl][jl] = m;
    }
    __syncthreads();

    const int bl2 = tid & 31;
#pragma unroll
    for (int rr = 0; rr < 4; rr++) {
        const int jl2 = (tid >> 5) + rr * 8;
        const uint32_t m = msk[bl2][jl2];
        size_t base = (size_t)(j0 + jl2) * NM + b0 + bl2;
#pragma unroll
        for (int t = 0; t < NT; t++)
            g_preT[base + t * NB] = ((m >> t) & 1u) ? 1.0f : 0.0f;
    }
}

// ---------------- GEMM-TT: C[m,n] = sum_k A[k][m]*B[k][n] -------------------
// A:[K][M] contiguous in m, B:[K][N] contiguous in n, C:[M][N].
// Tile 160x128x16, 256 threads, 10x8 microtile (8 rows + 2 extra rows).
// cp.async double-buffered smem, 1 sync per slab. Ascending-k exact.
#define TM 160
#define TN 128
#define TK 16

__global__ __launch_bounds__(256)
void gemm_tt(const float* __restrict__ A, const float* __restrict__ B,
             float* __restrict__ C, int M, int N, int K) {
    __shared__ float As[2][TK][TM];
    __shared__ float Bs[2][TK][TN];

    const int tid  = threadIdx.x;
    const int m0   = blockIdx.y * TM;
    const int n0   = blockIdx.x * TN;
    const int warp = tid >> 5;
    const int lane = tid & 31;
    const int wm   = warp & 1;       // 2 warp-rows (80 m each)
    const int wn   = warp >> 1;      // 4 warp-cols (32 n each)
    const int tmain  = wm * 80 + (lane & 7) * 8;        // 8 m rows
    const int textra = wm * 80 + 64 + (lane & 7) * 2;   // 2 m rows
    const int tn     = wn * 32 + (lane >> 3) * 8;       // 8 n cols

    float acc[10][8];
#pragma unroll
    for (int i = 0; i < 10; i++)
#pragma unroll
        for (int j = 0; j < 8; j++) acc[i][j] = 0.0f;

    // slab loader: A 640 16B-chunks (16k x 40), B 512 chunks (16k x 32)
    auto load_slab = [&](int kb, int s) {
        for (int c = tid; c < TK * (TM / 4); c += 256) {
            int k  = c / (TM / 4);
            int mc = c - k * (TM / 4);
            cp16(&As[s][k][mc * 4], A + (size_t)(kb + k) * M + m0 + mc * 4);
        }
        for (int c = tid; c < TK * (TN / 4); c += 256) {
            int k  = c >> 5;
            int nc = c & 31;
            cp16(&Bs[s][k][nc * 4], B + (size_t)(kb + k) * N + n0 + nc * 4);
        }
        cp_commit();
    };

    load_slab(0, 0);
    int stage = 0;
    for (int kb = 0; kb < K; kb += TK) {
        cp_wait0();
        __syncthreads();
        if (kb + TK < K) load_slab(kb + TK, stage ^ 1);

#pragma unroll
        for (int k = 0; k < TK; k++) {
            float4 a0 = *reinterpret_cast<const float4*>(&As[stage][k][tmain]);
            float4 a1 = *reinterpret_cast<const float4*>(&As[stage][k][tmain + 4]);
            float2 a2 = *reinterpret_cast<const float2*>(&As[stage][k][textra]);
            float4 b0 = *reinterpret_cast<const float4*>(&Bs[stage][k][tn]);
            float4 b1 = *reinterpret_cast<const float4*>(&Bs[stage][k][tn + 4]);
            float a[10] = {a0.x, a0.y, a0.z, a0.w, a1.x, a1.y, a1.z, a1.w, a2.x, a2.y};
            float b[8]  = {b0.x, b0.y, b0.z, b0.w, b1.x, b1.y, b1.z, b1.w};
#pragma unroll
            for (int i = 0; i < 10; i++)
#pragma unroll
                for (int j = 0; j < 8; j++)
                    acc[i][j] = __fmaf_rn(a[i], b[j], acc[i][j]);
        }
        stage ^= 1;
    }

#pragma unroll
    for (int i = 0; i < 8; i++) {
        float* crow = C + (size_t)(m0 + tmain + i) * N + n0 + tn;
        *reinterpret_cast<float4*>(crow)     = make_float4(acc[i][0], acc[i][1], acc[i][2], acc[i][3]);
        *reinterpret_cast<float4*>(crow + 4) = make_float4(acc[i][4], acc[i][5], acc[i][6], acc[i][7]);
    }
#pragma unroll
    for (int i = 0; i < 2; i++) {
        float* crow = C + (size_t)(m0 + textra + i) * N + n0 + tn;
        *reinterpret_cast<float4*>(crow)     = make_float4(acc[8 + i][0], acc[8 + i][1], acc[8 + i][2], acc[8 + i][3]);
        *reinterpret_cast<float4*>(crow + 4) = make_float4(acc[8 + i][4], acc[8 + i][5], acc[8 + i][6], acc[8 + i][7]);
    }
}

// ---------------- K3: LIF scan, writes S^T ----------------------------------
// grid (NHID/32, NB/32), 256 threads, same transpose pattern as k_gen.
__global__ __launch_bounds__(256) void k_lif() {
    __shared__ uint32_t msk[32][33];
    const int h0 = blockIdx.x * 32, b0 = blockIdx.y * 32;
    const int tid = threadIdx.x;

    const int hl = tid & 31;
#pragma unroll
    for (int r = 0; r < 4; r++) {
        const int bl = (tid >> 5) * 4 + r;
        float v = 0.0f;
        uint32_t m = 0;
#pragma unroll
        for (int t = 0; t < NT; t++) {
            float h = g_H[(size_t)(t * NB + b0 + bl) * NHID + h0 + hl];
            v = __fadd_rn(__fmul_rn(v, 0.3f), h);
            if (v >= 1.0f) { m |= (1u << t); v = 0.0f; }
        }
        msk[bl][hl] = m;
    }
    __syncthreads();

    const int bl2 = tid & 31;
#pragma unroll
    for (int rr = 0; rr < 4; rr++) {
        const int hl2 = (tid >> 5) + rr * 8;
        const uint32_t m = msk[bl2][hl2];
        size_t base = (size_t)(h0 + hl2) * NM + b0 + bl2;
#pragma unroll
        for (int t = 0; t < NT; t++)
            g_ST[base + t * NB] = ((m >> t) & 1u) ? 1.0f : 0.0f;
    }
}

// ---------------- K5: output spike counting ---------------------------------
__global__ __launch_bounds__(256) void k_count(const float* __restrict__ b_out,
                                               float* __restrict__ out) {
    int i = blockIdx.x * blockDim.x + threadIdx.x;
    if (i >= NB * NOUT) return;
    int o = i & (NOUT - 1);
    float bo = b_out[o];
    float s = 0.0f;
#pragma unroll
    for (int t = 0; t < NT; t++) {
        float val = __fadd_rn(g_O[(size_t)t * (NB * NOUT) + i], bo);
        s += (val > 0.0f) ? 1.0f : 0.0f;
    }
    out[i] = s;
}

// ---------------- launch ----------------------------------------------------
extern "C" void kernel_launch(void* const* d_in, const int* in_sizes, int n_in,
                              void* d_out, int out_size) {
    const float* x     = (const float*)d_in[0];
    const float* W_in  = (const float*)d_in[1];
    const float* W_out = (const float*)d_in[2];
    const float* b_out = (const float*)d_in[3];
    float* out = (float*)d_out;

    void *p_preT, *p_WinT, *p_H, *p_ST, *p_WoutT, *p_O;
    cudaGetSymbolAddress(&p_preT,  g_preT);
    cudaGetSymbolAddress(&p_WinT,  g_WinT);
    cudaGetSymbolAddress(&p_H,     g_H);
    cudaGetSymbolAddress(&p_ST,    g_ST);
    cudaGetSymbolAddress(&p_WoutT, g_WoutT);
    cudaGetSymbolAddress(&p_O,     g_O);

    k_keys<<<1, 32>>>();

    // transposes: W_inT[3072][2048] from W_in[2048][3072]; W_outT likewise
    k_transpose<<<dim3(NIN / 32, NHID / 32), 256>>>(W_in,  (float*)p_WinT,  NHID, NIN);
    k_transpose<<<dim3(NHID / 32, NOUT / 32), 256>>>(W_out, (float*)p_WoutT, NOUT, NHID);

    k_gen<<<dim3(NIN / 32, NB / 32), 256>>>(x);

    {   // H[5120,2048] = PRE^T' : A=g_preT [3072][5120], B=g_WinT [3072][2048]
        dim3 grid(NHID / TN, NM / TM);   // (16, 32) = 512 blocks
        gemm_tt<<<grid, 256>>>((const float*)p_preT, (const float*)p_WinT,
                               (float*)p_H, NM, NHID, NIN);
    }

    k_lif<<<dim3(NHID / 32, NB / 32), 256>>>();

    {   // O[5120,512] : A=g_ST [2048][5120], B=g_WoutT [2048][512]
        dim3 grid(NOUT / TN, NM / TM);   // (4, 32) = 128 blocks
        gemm_tt<<<grid, 256>>>((const float*)p_ST, (const float*)p_WoutT,
                               (float*)p_O, NM, NOUT, NHID);
    }

    k_count<<<(NB * NOUT + 255) / 256, 256>>>(b_out, out);
}

// round 4
// speedup vs baseline: 1.7454x; 1.3322x over previous
#include <cuda_runtime.h>
#include <cuda_bf16.h>
#include <cstdint>

// ============================================================================
// SpikingNetwork, T=10. B=512, input=3072, hidden=2048, out=512
// Tensor-core (bf16 mma.sync) GEMMs with 2-limb exact weight decomposition +
// threshold-margin flagging + exact sequential recompute of flagged elements.
//   w = hi(bf16) + mid(bf16) + lo,  |lo| <= 3.8e-6*|w|
//   spikes are exactly 0/1 in bf16 -> mma products exact; only accumulation
//   order + lo differ from reference => |h_tc - h_ref| << MARGIN.
//   Any v within MARGIN_V of threshold 1.0 (or out within MARGIN_O of 0) is
//   recomputed with the reference's exact ascending-k fp32 chain.
// ============================================================================

#define NB   512
#define NIN  3072
#define NHID 2048
#define NOUT 512
#define NT   10
#define NM   (NT * NB)     // 5120

#define MARGIN_V 3e-4f
#define MARGIN_O 1e-4f
#define CAPS 65536         // flagged (b,h) pairs cap (~40x headroom)
#define CAPO 65536         // flagged (t,b,o) cap

__device__ __align__(16) __nv_bfloat16 g_Pre [NM * NIN];     // [m=(t,b)][j]
__device__ __align__(16) __nv_bfloat16 g_S   [NM * NHID];    // [m=(t,b)][h]
__device__ __align__(16) __nv_bfloat16 g_WinHi [NHID * NIN];
__device__ __align__(16) __nv_bfloat16 g_WinMid[NHID * NIN];
__device__ __align__(16) __nv_bfloat16 g_WoutHi [NOUT * NHID];
__device__ __align__(16) __nv_bfloat16 g_WoutMid[NOUT * NHID];
__device__ float    g_H[NM * NHID];
__device__ float    g_O[NM * NOUT];
__device__ uint16_t g_jmask[NB * NIN];    // 10 spike bits per (b,j)
__device__ uint16_t g_smask[NB * NHID];   // 10 spike bits per (b,h)
__device__ uint32_t g_k0[NT];
__device__ uint32_t g_k1[NT];
__device__ int      g_nflagS;
__device__ int      g_flagS[CAPS];
__device__ float    g_fixH[CAPS * NT];
__device__ int      g_nflagO;
__device__ int      g_flagO[CAPO];

// ---------------- threefry2x32 (JAX-exact, 20 rounds) -----------------------
__device__ __forceinline__ uint32_t rotl32(uint32_t x, int r) {
    return __funnelshift_l(x, x, r);
}
__device__ __forceinline__ void threefry2x32(uint32_t k0, uint32_t k1,
                                             uint32_t x0, uint32_t x1,
                                             uint32_t& o0, uint32_t& o1) {
    uint32_t ks2 = k0 ^ k1 ^ 0x1BD11BDAu;
    x0 += k0; x1 += k1;
#define TF_R(r) { x0 += x1; x1 = rotl32(x1, (r)); x1 ^= x0; }
    TF_R(13) TF_R(15) TF_R(26) TF_R(6)
    x0 += k1;  x1 += ks2 + 1u;
    TF_R(17) TF_R(29) TF_R(16) TF_R(24)
    x0 += ks2; x1 += k0 + 2u;
    TF_R(13) TF_R(15) TF_R(26) TF_R(6)
    x0 += k0;  x1 += k1 + 3u;
    TF_R(17) TF_R(29) TF_R(16) TF_R(24)
    x0 += k1;  x1 += ks2 + 4u;
    TF_R(13) TF_R(15) TF_R(26) TF_R(6)
    x0 += ks2; x1 += k0 + 5u;
#undef TF_R
    o0 = x0; o1 = x1;
}

// ---------------- XLA logistic ----------------------------------------------
__device__ __forceinline__ float xla_tanh_f32(float x) {
    const float kClamp = 7.90531110763549805f;
    float ax = fabsf(x);
    float xc = fminf(fmaxf(x, -kClamp), kClamp);
    float x2 = __fmul_rn(xc, xc);
    float p;
    p = __fadd_rn(__fmul_rn(x2, -2.76076847742355e-16f), 2.00018790482477e-13f);
    p = __fadd_rn(__fmul_rn(x2, p), -8.60467152213735e-11f);
    p = __fadd_rn(__fmul_rn(x2, p),  5.12229709037114e-08f);
    p = __fadd_rn(__fmul_rn(x2, p),  1.48572235717979e-05f);
    p = __fadd_rn(__fmul_rn(x2, p),  6.37261928875436e-04f);
    p = __fadd_rn(__fmul_rn(x2, p),  4.89352455891786e-03f);
    p = __fmul_rn(xc, p);
    float q;
    q = __fadd_rn(__fmul_rn(x2, 1.19825839466702e-06f), 1.18534705686654e-04f);
    q = __fadd_rn(__fmul_rn(x2, q), 2.26843463243900e-03f);
    q = __fadd_rn(__fmul_rn(x2, q), 4.89352518554385e-03f);
    float t = __fdiv_rn(p, q);
    return (ax < 0.0004f) ? x : t;
}
__device__ __forceinline__ float xla_sigmoid_f32(float x) {
    float t = xla_tanh_f32(__fmul_rn(x, 0.5f));
    return __fadd_rn(0.5f, __fmul_rn(0.5f, t));
}

// ---------------- cp.async --------------------------------------------------
__device__ __forceinline__ void cp16(void* dst_smem, const void* src) {
    uint32_t d = (uint32_t)__cvta_generic_to_shared(dst_smem);
    asm volatile("cp.async.cg.shared.global [%0], [%1], 16;\n" :: "r"(d), "l"(src));
}
__device__ __forceinline__ void cp_commit() { asm volatile("cp.async.commit_group;\n"); }
__device__ __forceinline__ void cp_wait1()  { asm volatile("cp.async.wait_group 1;\n"); }
__device__ __forceinline__ void cp_wait0()  { asm volatile("cp.async.wait_group 0;\n"); }

// ---------------- bf16 mma m16n8k16 -----------------------------------------
__device__ __forceinline__ void mma16816(float& d0, float& d1, float& d2, float& d3,
                                         uint32_t a0, uint32_t a1, uint32_t a2, uint32_t a3,
                                         uint32_t b0, uint32_t b1) {
    asm volatile(
        "mma.sync.aligned.m16n8k16.row.col.f32.bf16.bf16.f32 "
        "{%0,%1,%2,%3},{%4,%5,%6,%7},{%8,%9},{%0,%1,%2,%3};"
        : "+f"(d0), "+f"(d1), "+f"(d2), "+f"(d3)
        : "r"(a0), "r"(a1), "r"(a2), "r"(a3), "r"(b0), "r"(b1));
}

// ---------------- setup kernels ---------------------------------------------
__global__ void k_zero() { g_nflagS = 0; g_nflagO = 0; }

__global__ void k_keys() {
    int t = threadIdx.x;
    if (t < NT) {
        uint32_t a, b;
        threefry2x32(0u, 42u, 0u, (uint32_t)t, a, b);
        g_k0[t] = a; g_k1[t] = b;
    }
}

// exact 2-limb split: hi = bf16(w), mid = bf16(w - hi); w-hi exact in fp32
__global__ __launch_bounds__(256) void k_limbs(const float* __restrict__ W,
                                               __nv_bfloat16* __restrict__ Hi,
                                               __nv_bfloat16* __restrict__ Mid, int n) {
    int i = blockIdx.x * blockDim.x + threadIdx.x;
    if (i >= n) return;
    float w = W[i];
    __nv_bfloat16 h = __float2bfloat16(w);
    float r = __fadd_rn(w, -__bfloat162float(h));
    Hi[i] = h;
    Mid[i] = __float2bfloat16(r);
}

// ---------------- K1: stochastic input spikes -> g_Pre bf16 + masks ---------
__global__ __launch_bounds__(256) void k_gen(const float* __restrict__ x) {
    int idx = blockIdx.x * blockDim.x + threadIdx.x;
    if (idx >= NB * NIN) return;
    int b = idx / NIN, j = idx - b * NIN;
    float p = xla_sigmoid_f32(x[idx]);
    uint32_t m = 0;
#pragma unroll
    for (int t = 0; t < NT; t++) {
        uint32_t a, bb;
        threefry2x32(g_k0[t], g_k1[t], 0u, (uint32_t)idx, a, bb);
        uint32_t bits = a ^ bb;
        float u = __uint_as_float((bits >> 9) | 0x3F800000u) - 1.0f;
        m |= (u < p) ? (1u << t) : 0u;
    }
    g_jmask[idx] = (uint16_t)m;
    const __nv_bfloat16 one = __float2bfloat16(1.0f);
    const __nv_bfloat16 zero = __float2bfloat16(0.0f);
#pragma unroll
    for (int t = 0; t < NT; t++)
        g_Pre[(size_t)(t * NB + b) * NIN + j] = ((m >> t) & 1u) ? one : zero;
}

// ---------------- bf16 2-limb tensor-core GEMM ------------------------------
// C[m][n] = sum_k A[m][k] * (BH[n][k] + BM[n][k]),  A row-major, B [n][k].
// CTA tile 128x128x32, 8 warps (2m x 4n), warp tile 64x32, mma m16n8k16.
// Padded smem rows (40 halves) -> conflict-free LDS.32 fragment loads.
#define GTK 32
#define ROWH 40   // halves per smem row (32 data + 8 pad); 80B = 5*16B

__global__ __launch_bounds__(256)
void gemm_mma(const __nv_bfloat16* __restrict__ A,
              const __nv_bfloat16* __restrict__ BH,
              const __nv_bfloat16* __restrict__ BM,
              float* __restrict__ C, int M, int N, int K) {
    extern __shared__ __nv_bfloat16 sm[];
    __nv_bfloat16* As  = sm;                    // [2][128][ROWH]
    __nv_bfloat16* BsH = sm + 2 * 128 * ROWH;
    __nv_bfloat16* BsM = sm + 4 * 128 * ROWH;

    const int tid  = threadIdx.x;
    const int m0   = blockIdx.y * 128;
    const int n0   = blockIdx.x * 128;
    const int warp = tid >> 5;
    const int lane = tid & 31;
    const int wm   = (warp & 1) * 64;
    const int wn   = (warp >> 3 == 0 ? (warp >> 1) : 0) * 32; // warp>>1 in 0..3
    const int r    = lane >> 2;
    const int c2   = (lane & 3) * 2;

    float acc[4][4][4];
#pragma unroll
    for (int mi = 0; mi < 4; mi++)
#pragma unroll
        for (int nj = 0; nj < 4; nj++)
#pragma unroll
            for (int q = 0; q < 4; q++) acc[mi][nj][q] = 0.0f;

    auto issue_slab = [&](int kb, int s) {
#pragma unroll
        for (int it = 0; it < 2; it++) {
            int idx = it * 256 + tid;
            int row = idx >> 2;
            int ch  = idx & 3;
            size_t go = (size_t)row * K + kb + ch * 8;
            int so = (s * 128 + row) * ROWH + ch * 8;
            cp16(&As[so],  A  + (size_t)m0 * K + go);
            cp16(&BsH[so], BH + (size_t)n0 * K + go);
            cp16(&BsM[so], BM + (size_t)n0 * K + go);
        }
        cp_commit();
    };

    const int nslab = K / GTK;
    issue_slab(0, 0);
    int s = 0;
    for (int sl = 0; sl < nslab; sl++) {
        if (sl + 1 < nslab) { issue_slab((sl + 1) * GTK, s ^ 1); cp_wait1(); }
        else                { cp_wait0(); }
        __syncthreads();

#pragma unroll
        for (int kc = 0; kc < 2; kc++) {   // two k16 steps in the 32-k slab
            const int kh = kc * 16;
            uint32_t af[4][4];
#pragma unroll
            for (int mi = 0; mi < 4; mi++) {
                const __nv_bfloat16* base = &As[(s * 128 + wm + 16 * mi) * ROWH + kh];
                af[mi][0] = *(const uint32_t*)&base[(size_t)(r)     * ROWH + c2];
                af[mi][1] = *(const uint32_t*)&base[(size_t)(r + 8) * ROWH + c2];
                af[mi][2] = *(const uint32_t*)&base[(size_t)(r)     * ROWH + c2 + 8];
                af[mi][3] = *(const uint32_t*)&base[(size_t)(r + 8) * ROWH + c2 + 8];
            }
            uint32_t bf[4][2];
#pragma unroll
            for (int nj = 0; nj < 4; nj++) {
                const __nv_bfloat16* base = &BsH[(s * 128 + wn + 8 * nj + r) * ROWH + kh];
                bf[nj][0] = *(const uint32_t*)&base[c2];
                bf[nj][1] = *(const uint32_t*)&base[c2 + 8];
            }
#pragma unroll
            for (int mi = 0; mi < 4; mi++)
#pragma unroll
                for (int nj = 0; nj < 4; nj++)
                    mma16816(acc[mi][nj][0], acc[mi][nj][1], acc[mi][nj][2], acc[mi][nj][3],
                             af[mi][0], af[mi][1], af[mi][2], af[mi][3],
                             bf[nj][0], bf[nj][1]);
#pragma unroll
            for (int nj = 0; nj < 4; nj++) {
                const __nv_bfloat16* base = &BsM[(s * 128 + wn + 8 * nj + r) * ROWH + kh];
                bf[nj][0] = *(const uint32_t*)&base[c2];
                bf[nj][1] = *(const uint32_t*)&base[c2 + 8];
            }
#pragma unroll
            for (int mi = 0; mi < 4; mi++)
#pragma unroll
                for (int nj = 0; nj < 4; nj++)
                    mma16816(acc[mi][nj][0], acc[mi][nj][1], acc[mi][nj][2], acc[mi][nj][3],
                             af[mi][0], af[mi][1], af[mi][2], af[mi][3],
                             bf[nj][0], bf[nj][1]);
        }
        __syncthreads();
        if (sl + 1 < nslab) s ^= 1;
    }

#pragma unroll
    for (int mi = 0; mi < 4; mi++)
#pragma unroll
        for (int nj = 0; nj < 4; nj++) {
            int row = m0 + wm + 16 * mi + r;
            int col = n0 + wn + 8 * nj + c2;
            *(float2*)&C[(size_t)row * N + col] =
                make_float2(acc[mi][nj][0], acc[mi][nj][1]);
            *(float2*)&C[(size_t)(row + 8) * N + col] =
                make_float2(acc[mi][nj][2], acc[mi][nj][3]);
        }
}

// ---------------- K3: LIF scan + flagging -----------------------------------
__global__ __launch_bounds__(256) void k_lif() {
    int i = blockIdx.x * blockDim.x + threadIdx.x;
    if (i >= NB * NHID) return;
    int b = i >> 11, h = i & (NHID - 1);
    float v = 0.0f;
    uint32_t m = 0;
    bool flag = false;
#pragma unroll
    for (int t = 0; t < NT; t++) {
        float hv = g_H[(size_t)(t * NB + b) * NHID + h];
        v = __fadd_rn(__fmul_rn(v, 0.3f), hv);
        flag |= fabsf(v - 1.0f) < MARGIN_V;
        if (v >= 1.0f) { m |= (1u << t); v = 0.0f; }
    }
    g_smask[i] = (uint16_t)m;
    const __nv_bfloat16 one = __float2bfloat16(1.0f);
    const __nv_bfloat16 zero = __float2bfloat16(0.0f);
#pragma unroll
    for (int t = 0; t < NT; t++)
        g_S[(size_t)(t * NB + b) * NHID + h] = ((m >> t) & 1u) ? one : zero;
    if (flag) {
        int pos = atomicAdd(&g_nflagS, 1);
        if (pos < CAPS) g_flagS[pos] = i;
    }
}

// exact h for flagged pairs: one thread per (pair, t), ascending-j chain
__global__ __launch_bounds__(256) void k_fixS1(const float* __restrict__ W_in) {
    int idx = blockIdx.x * blockDim.x + threadIdx.x;
    int n = g_nflagS; if (n > CAPS) n = CAPS;
    int pr = idx / NT, t = idx - pr * NT;
    if (pr >= n) return;
    int i = g_flagS[pr];
    int b = i >> 11, h = i & (NHID - 1);
    const uint16_t* mrow = g_jmask + (size_t)b * NIN;
    const float* wrow = W_in + (size_t)h * NIN;
    float acc = 0.0f;
    for (int j = 0; j < NIN; j++) {
        float w = wrow[j];
        acc = __fadd_rn(acc, ((mrow[j] >> t) & 1u) ? w : 0.0f);
    }
    g_fixH[pr * NT + t] = acc;
}

// exact v-chain + spike rewrite for flagged pairs
__global__ __launch_bounds__(256) void k_fixS2() {
    int idx = blockIdx.x * blockDim.x + threadIdx.x;
    int n = g_nflagS; if (n > CAPS) n = CAPS;
    if (idx >= n) return;
    int i = g_flagS[idx];
    int b = i >> 11, h = i & (NHID - 1);
    float v = 0.0f;
    uint32_t m = 0;
#pragma unroll
    for (int t = 0; t < NT; t++) {
        v = __fadd_rn(__fmul_rn(v, 0.3f), g_fixH[idx * NT + t]);
        if (v >= 1.0f) { m |= (1u << t); v = 0.0f; }
    }
    g_smask[i] = (uint16_t)m;
    const __nv_bfloat16 one = __float2bfloat16(1.0f);
    const __nv_bfloat16 zero = __float2bfloat16(0.0f);
#pragma unroll
    for (int t = 0; t < NT; t++)
        g_S[(size_t)(t * NB + b) * NHID + h] = ((m >> t) & 1u) ? one : zero;
}

// ---------------- output flag + exact fix + count ---------------------------
__global__ __launch_bounds__(256) void k_flagO(const float* __restrict__ b_out) {
    int i = blockIdx.x * blockDim.x + threadIdx.x;
    if (i >= NM * NOUT) return;
    float val = __fadd_rn(g_O[i], b_out[i & (NOUT - 1)]);
    if (fabsf(val) < MARGIN_O) {
        int pos = atomicAdd(&g_nflagO, 1);
        if (pos < CAPO) g_flagO[pos] = i;
    }
}

__global__ __launch_bounds__(256) void k_fixO(const float* __restrict__ W_out) {
    int idx = blockIdx.x * blockDim.x + threadIdx.x;
    int n = g_nflagO; if (n > CAPO) n = CAPO;
    if (idx >= n) return;
    int i = g_flagO[idx];
    int m = i / NOUT, o = i - m * NOUT;
    int b = m & (NB - 1), t = m / NB;
    const uint16_t* srow = g_smask + (size_t)b * NHID;
    const float* wrow = W_out + (size_t)o * NHID;
    float acc = 0.0f;
    for (int h = 0; h < NHID; h++) {
        float w = wrow[h];
        acc = __fadd_rn(acc, ((srow[h] >> t) & 1u) ? w : 0.0f);
    }
    g_O[i] = acc;
}

__global__ __launch_bounds__(256) void k_count(const float* __restrict__ b_out,
                                               float* __restrict__ out) {
    int i = blockIdx.x * blockDim.x + threadIdx.x;
    if (i >= NB * NOUT) return;
    float bo = b_out[i & (NOUT - 1)];
    float s = 0.0f;
#pragma unroll
    for (int t = 0; t < NT; t++) {
        float val = __fadd_rn(g_O[(size_t)t * (NB * NOUT) + i], bo);
        s += (val > 0.0f) ? 1.0f : 0.0f;
    }
    out[i] = s;
}

// ---------------- launch ----------------------------------------------------
extern "C" void kernel_launch(void* const* d_in, const int* in_sizes, int n_in,
                              void* d_out, int out_size) {
    const float* x     = (const float*)d_in[0];
    const float* W_in  = (const float*)d_in[1];
    const float* W_out = (const float*)d_in[2];
    const float* b_out = (const float*)d_in[3];
    float* out = (float*)d_out;

    static bool attr_set = false;
    const int smem_bytes = 6 * 128 * ROWH * 2;   // 61440
    if (!attr_set) {
        cudaFuncSetAttribute(gemm_mma, cudaFuncAttributeMaxDynamicSharedMemorySize,
                             smem_bytes);
        attr_set = true;
    }

    void *p_Pre, *p_S, *p_WiH, *p_WiM, *p_WoH, *p_WoM, *p_H, *p_O;
    cudaGetSymbolAddress(&p_Pre, g_Pre);
    cudaGetSymbolAddress(&p_S,   g_S);
    cudaGetSymbolAddress(&p_WiH, g_WinHi);
    cudaGetSymbolAddress(&p_WiM, g_WinMid);
    cudaGetSymbolAddress(&p_WoH, g_WoutHi);
    cudaGetSymbolAddress(&p_WoM, g_WoutMid);
    cudaGetSymbolAddress(&p_H,   g_H);
    cudaGetSymbolAddress(&p_O,   g_O);

    k_zero<<<1, 1>>>();
    k_keys<<<1, 32>>>();
    k_limbs<<<(NHID * NIN + 255) / 256, 256>>>(W_in,
        (__nv_bfloat16*)p_WiH, (__nv_bfloat16*)p_WiM, NHID * NIN);
    k_limbs<<<(NOUT * NHID + 255) / 256, 256>>>(W_out,
        (__nv_bfloat16*)p_WoH, (__nv_bfloat16*)p_WoM, NOUT * NHID);
    k_gen<<<(NB * NIN + 255) / 256, 256>>>(x);

    {   // H = PRE @ W_in^T
        dim3 grid(NHID / 128, NM / 128);
        gemm_mma<<<grid, 256, smem_bytes>>>((const __nv_bfloat16*)p_Pre,
            (const __nv_bfloat16*)p_WiH, (const __nv_bfloat16*)p_WiM,
            (float*)p_H, NM, NHID, NIN);
    }

    k_lif<<<(NB * NHID + 255) / 256, 256>>>();
    k_fixS1<<<(CAPS * NT + 255) / 256, 256>>>(W_in);
    k_fixS2<<<(CAPS + 255) / 256, 256>>>();

    {   // O = S @ W_out^T
        dim3 grid(NOUT / 128, NM / 128);
        gemm_mma<<<grid, 256, smem_bytes>>>((const __nv_bfloat16*)p_S,
            (const __nv_bfloat16*)p_WoH, (const __nv_bfloat16*)p_WoM,
            (float*)p_O, NM, NOUT, NHID);
    }

    k_flagO<<<(NM * NOUT + 255) / 256, 256>>>(b_out);
    k_fixO<<<(CAPO + 255) / 256, 256>>>(W_out);
    k_count<<<(NB * NOUT + 255) / 256, 256>>>(b_out, out);
}